// round 2
// baseline (speedup 1.0000x reference)
#include <cuda_runtime.h>
#include <math.h>

// GaussianQuantRegularizer2: fused per-row Gaussian-logprob codebook argmax
// + KL mean, with f32x2 packed FMA inner loop over a smem codebook.
//
// Key identities used:
//  - output zhat == prior_samples[idx]  (STE cancels zhat_g numerically)
//  - kl_loss == mean(kl2)               (ge+eq+le == 1 with lam=1)
//  - argmax score reduces to a 16-dim dot: f=[inv_var-1, mu*inv_var] vs
//    g_k=[-0.5*s^2, s]; all per-row constants and lp_k fold away.

#define THREADS 256
#define NBLOCKS 444            // 148 SMs * 3 blocks/SM
#define NPAIRS  512            // 1024 codes as 512 f32x2 pairs

__device__ float g_partials[NBLOCKS];

static __device__ __forceinline__ unsigned long long pack2f(float lo, float hi) {
    unsigned long long r;
    asm("mov.b64 %0, {%1, %2};" : "=l"(r) : "f"(lo), "f"(hi));
    return r;
}
static __device__ __forceinline__ void unpack2f(unsigned long long v, float &lo, float &hi) {
    asm("mov.b64 {%0, %1}, %2;" : "=f"(lo), "=f"(hi) : "l"(v));
}
static __device__ __forceinline__ unsigned long long ffma2(unsigned long long a,
                                                           unsigned long long b,
                                                           unsigned long long c) {
    unsigned long long d;
    asm("fma.rn.f32x2 %0, %1, %2, %3;" : "=l"(d) : "l"(a), "l"(b), "l"(c));
    return d;
}
static __device__ __forceinline__ unsigned long long fadd2(unsigned long long a,
                                                           unsigned long long b) {
    unsigned long long d;
    asm("add.rn.f32x2 %0, %1, %2;" : "=l"(d) : "l"(a), "l"(b));
    return d;
}

__global__ __launch_bounds__(THREADS, 3)
void gqr_main(const float* __restrict__ z, const float* __restrict__ prior,
              float* __restrict__ out, int nrows, long long idx_off)
{
    // Codebook: [pair p][dim-pair jj] -> float4 (gA_t0, gB_t0, gA_t1, gB_t1)
    // stored as ulonglong2 so LDS.128 lands directly in two f32x2 operands.
    extern __shared__ ulonglong2 cb[];   // NPAIRS*8 entries = 64 KB

    for (int e = threadIdx.x; e < NPAIRS * 8; e += THREADS) {
        int p  = e >> 3, jj = e & 7;
        int k0 = p * 2, k1 = k0 + 1;
        int t0 = jj * 2, t1 = t0 + 1;
        float a0, b0, a1, b1;
        if (t0 < 8) {   // quadratic features: -0.5 * s^2
            float x  = prior[k0 * 8 + t0]; a0 = -0.5f * x  * x;
            float y  = prior[k1 * 8 + t0]; b0 = -0.5f * y  * y;
            float x1 = prior[k0 * 8 + t1]; a1 = -0.5f * x1 * x1;
            float y1 = prior[k1 * 8 + t1]; b1 = -0.5f * y1 * y1;
        } else {        // linear features: s
            a0 = prior[k0 * 8 + t0 - 8]; b0 = prior[k1 * 8 + t0 - 8];
            a1 = prior[k0 * 8 + t1 - 8]; b1 = prior[k1 * 8 + t1 - 8];
        }
        ulonglong2 q; q.x = pack2f(a0, b0); q.y = pack2f(a1, b1);
        cb[e] = q;
    }
    __syncthreads();

    // Balanced contiguous row partition across NBLOCKS.
    int base  = nrows / NBLOCKS;
    int rem   = nrows - base * NBLOCKS;
    int blk   = blockIdx.x;
    int start = blk * base + min(blk, rem);
    int cnt   = base + (blk < rem ? 1 : 0);

    float klacc = 0.0f;

    for (int r = threadIdx.x; r < cnt; r += THREADS) {
        int n  = start + r;
        int bb = n >> 12;          // batch (H*W = 4096)
        int hw = n & 4095;
        const float* zp = z + ((size_t)bb << 16) + hw;   // z[b, c, h, w]

        unsigned long long fp[16];
        #pragma unroll
        for (int d = 0; d < 8; d++) {
            float mu = zp[(size_t)d << 12];
            float lv = zp[(size_t)(8 + d) << 12];
            lv = fminf(fmaxf(lv, -30.0f), 20.0f);
            float var = expf(lv);
            float iv  = 1.0f / var;
            float fq  = iv - 1.0f;
            float fl  = mu * iv;
            fp[d]     = pack2f(fq, fq);
            fp[8 + d] = pack2f(fl, fl);
            klacc += mu * mu + var - 1.0f - lv;
        }

        float best = -3.402823466e38f;
        int   bidx = 0;
        const ulonglong2* cp = cb;
        for (int p = 0; p < NPAIRS; p++) {
            unsigned long long accA = 0ULL, accB = 0ULL;  // two chains for ILP
            #pragma unroll
            for (int jj = 0; jj < 8; jj++) {
                ulonglong2 q = cp[jj];
                accA = ffma2(fp[2 * jj],     q.x, accA);
                accB = ffma2(fp[2 * jj + 1], q.y, accB);
            }
            cp += 8;
            float s0, s1;
            unpack2f(fadd2(accA, accB), s0, s1);
            // strict '>' preserves jnp.argmax first-max tie rule
            if (s0 > best) { best = s0; bidx = 2 * p; }
            if (s1 > best) { best = s1; bidx = 2 * p + 1; }
        }

        // zhat[b, d, h, w] = prior[bidx, d]
        const float* pv = prior + (size_t)bidx * 8;
        #pragma unroll
        for (int d = 0; d < 8; d++)
            out[(((size_t)(bb * 8 + d)) << 12) + hw] = pv[d];

        out[idx_off + n] = (float)bidx;
    }

    // block-level KL partial (deterministic two-pass; no float atomics)
    #pragma unroll
    for (int o = 16; o > 0; o >>= 1)
        klacc += __shfl_down_sync(0xFFFFFFFFu, klacc, o);
    __shared__ float red[THREADS / 32];
    if ((threadIdx.x & 31) == 0) red[threadIdx.x >> 5] = klacc;
    __syncthreads();
    if (threadIdx.x == 0) {
        float s = 0.0f;
        #pragma unroll
        for (int i = 0; i < THREADS / 32; i++) s += red[i];
        g_partials[blockIdx.x] = s;
    }
}

__global__ void gqr_finalize(float* __restrict__ out, long long kl_off, float scale)
{
    __shared__ float red[16];
    float s = 0.0f;
    for (int i = threadIdx.x; i < NBLOCKS; i += blockDim.x) s += g_partials[i];
    #pragma unroll
    for (int o = 16; o > 0; o >>= 1)
        s += __shfl_down_sync(0xFFFFFFFFu, s, o);
    if ((threadIdx.x & 31) == 0) red[threadIdx.x >> 5] = s;
    __syncthreads();
    if (threadIdx.x == 0) {
        float t = 0.0f;
        int nw = blockDim.x >> 5;
        for (int i = 0; i < nw; i++) t += red[i];
        out[kl_off] = t * scale;
    }
}

extern "C" void kernel_launch(void* const* d_in, const int* in_sizes, int n_in,
                              void* d_out, int out_size)
{
    const float* z     = (const float*)d_in[0];
    // d_in[1] (noise) is provably unused by the forward values.
    const float* prior = (const float*)d_in[2];
    float* out = (float*)d_out;

    int nrows = in_sizes[0] / 16;                       // 131072
    long long idx_off = (long long)out_size - (long long)nrows;
    if (idx_off < 1) idx_off = 1;                       // defensive clamp
    long long kl_off  = idx_off - 1;                    // scalar just before it

    (void)cudaFuncSetAttribute(gqr_main,
                               cudaFuncAttributeMaxDynamicSharedMemorySize, 65536);
    gqr_main<<<NBLOCKS, THREADS, 65536>>>(z, prior, out, nrows, idx_off);

    float scale = (1.4426f * 0.5f) / (float)nrows;
    gqr_finalize<<<1, 512>>>(out, kl_off, scale);
}

// round 4
// speedup vs baseline: 1.2305x; 1.2305x over previous
#include <cuda_runtime.h>
#include <math.h>
#include <float.h>

// GaussianQuantRegularizer2 — fused codebook argmax + KL mean.
// R4: R3 design (two rows per thread; codebook LDS amortized across the row
// pair -> fma-pipe-bound) with the fp[r][0]-clobber bug removed.
//
// Identities: zhat == prior[idx] (STE cancels), kl_loss == mean(kl2)
// (ge+eq+le==1), argmax score == 16-dim dot f=[iv-1, mu*iv] . g_k=[-s^2/2, s].

#define THREADS 256
#define NPAIRS  512            // 1024 codes as 512 f32x2 code-pairs
#define MAXBLK  512

__device__ float g_partials[MAXBLK];

static __device__ __forceinline__ unsigned long long pack2f(float lo, float hi) {
    unsigned long long r;
    asm("mov.b64 %0, {%1, %2};" : "=l"(r) : "f"(lo), "f"(hi));
    return r;
}
static __device__ __forceinline__ void unpack2f(unsigned long long v, float &lo, float &hi) {
    asm("mov.b64 {%0, %1}, %2;" : "=f"(lo), "=f"(hi) : "l"(v));
}
static __device__ __forceinline__ unsigned long long ffma2(unsigned long long a,
                                                           unsigned long long b,
                                                           unsigned long long c) {
    unsigned long long d;
    asm("fma.rn.f32x2 %0, %1, %2, %3;" : "=l"(d) : "l"(a), "l"(b), "l"(c));
    return d;
}
static __device__ __forceinline__ unsigned long long fmul2(unsigned long long a,
                                                           unsigned long long b) {
    unsigned long long d;
    asm("mul.rn.f32x2 %0, %1, %2;" : "=l"(d) : "l"(a), "l"(b));
    return d;
}
static __device__ __forceinline__ unsigned long long fadd2(unsigned long long a,
                                                           unsigned long long b) {
    unsigned long long d;
    asm("add.rn.f32x2 %0, %1, %2;" : "=l"(d) : "l"(a), "l"(b));
    return d;
}

__global__ __launch_bounds__(THREADS, 2)
void gqr_main(const float* __restrict__ z, const float* __restrict__ prior,
              float* __restrict__ out, int nrows, long long idx_off)
{
    // Codebook: [pair p][jj] -> ulonglong2 {(gA_t0,gB_t0),(gA_t1,gB_t1)},
    // t = 2jj, 2jj+1 over 16 features; A = code 2p, B = code 2p+1.
    extern __shared__ ulonglong2 cb[];   // 512*8 entries = 64 KB

    for (int e = threadIdx.x; e < NPAIRS * 8; e += THREADS) {
        int p  = e >> 3, jj = e & 7;
        int k0 = p * 2, k1 = k0 + 1;
        int t0 = jj * 2, t1 = t0 + 1;
        float a0, b0, a1, b1;
        if (t0 < 8) {   // quadratic features: -0.5 * s^2
            float x  = prior[k0 * 8 + t0]; a0 = -0.5f * x  * x;
            float y  = prior[k1 * 8 + t0]; b0 = -0.5f * y  * y;
            float x1 = prior[k0 * 8 + t1]; a1 = -0.5f * x1 * x1;
            float y1 = prior[k1 * 8 + t1]; b1 = -0.5f * y1 * y1;
        } else {        // linear features: s
            a0 = prior[k0 * 8 + t0 - 8]; b0 = prior[k1 * 8 + t0 - 8];
            a1 = prior[k0 * 8 + t1 - 8]; b1 = prior[k1 * 8 + t1 - 8];
        }
        ulonglong2 q; q.x = pack2f(a0, b0); q.y = pack2f(a1, b1);
        cb[e] = q;
    }
    __syncthreads();

    int t = blockIdx.x * THREADS + threadIdx.x;   // one row-PAIR per thread
    int npr = nrows >> 1;
    float klacc = 0.0f;

    if (t < npr) {
        int n0 = t << 1;
        int bb = n0 >> 12;          // H*W = 4096
        int hw = n0 & 4095;         // even -> rows n0, n0+1 share bb
        const float* zp = z + ((size_t)bb << 16) + hw;

        unsigned long long fp[2][16];
        #pragma unroll
        for (int d = 0; d < 8; d++) {
            float2 mu2 = *(const float2*)(zp + ((size_t)d << 12));
            float2 lv2 = *(const float2*)(zp + ((size_t)(8 + d) << 12));
            #pragma unroll
            for (int r = 0; r < 2; r++) {
                float mu = r ? mu2.y : mu2.x;
                float lv = r ? lv2.y : lv2.x;
                lv = fminf(fmaxf(lv, -30.0f), 20.0f);
                float var = expf(lv);
                float iv  = 1.0f / var;
                float fq  = iv - 1.0f;
                float fl  = mu * iv;
                fp[r][d]     = pack2f(fq, fq);
                fp[r][8 + d] = pack2f(fl, fl);
                klacc += mu * mu + var - 1.0f - lv;
            }
        }

        // even/odd running max per row; strict '>' keeps first-max per half
        float bestE[2] = { -FLT_MAX, -FLT_MAX };
        float bestO[2] = { -FLT_MAX, -FLT_MAX };
        int   pE[2] = { 0, 0 }, pO[2] = { 0, 0 };

        const ulonglong2* cp = cb;
        #pragma unroll 2
        for (int p = 0; p < NPAIRS; p++) {
            ulonglong2 q[8];
            #pragma unroll
            for (int jj = 0; jj < 8; jj++) q[jj] = cp[jj];
            cp += 8;
            #pragma unroll
            for (int r = 0; r < 2; r++) {
                unsigned long long a0 = fmul2(fp[r][0], q[0].x);
                unsigned long long a1 = fmul2(fp[r][1], q[0].y);
                #pragma unroll
                for (int jj = 1; jj < 8; jj++) {
                    a0 = ffma2(fp[r][2 * jj],     q[jj].x, a0);
                    a1 = ffma2(fp[r][2 * jj + 1], q[jj].y, a1);
                }
                float s0, s1;
                unpack2f(fadd2(a0, a1), s0, s1);
                if (s0 > bestE[r]) { bestE[r] = s0; pE[r] = p; }
                if (s1 > bestO[r]) { bestO[r] = s1; pO[r] = p; }
            }
        }

        int idx[2];
        #pragma unroll
        for (int r = 0; r < 2; r++) {
            int ie = 2 * pE[r], io = 2 * pO[r] + 1;
            if (bestO[r] > bestE[r])      idx[r] = io;
            else if (bestO[r] < bestE[r]) idx[r] = ie;
            else                          idx[r] = min(ie, io);  // first-max tie
        }

        const float* pvA = prior + (size_t)idx[0] * 8;
        const float* pvB = prior + (size_t)idx[1] * 8;
        #pragma unroll
        for (int d = 0; d < 8; d++) {
            float2 o; o.x = pvA[d]; o.y = pvB[d];
            *(float2*)(out + (((size_t)(bb * 8 + d)) << 12) + hw) = o;
        }
        out[idx_off + n0]     = (float)idx[0];
        out[idx_off + n0 + 1] = (float)idx[1];
    }

    // deterministic block-level KL partial
    #pragma unroll
    for (int o = 16; o > 0; o >>= 1)
        klacc += __shfl_down_sync(0xFFFFFFFFu, klacc, o);
    __shared__ float red[THREADS / 32];
    if ((threadIdx.x & 31) == 0) red[threadIdx.x >> 5] = klacc;
    __syncthreads();
    if (threadIdx.x == 0) {
        float s = 0.0f;
        #pragma unroll
        for (int i = 0; i < THREADS / 32; i++) s += red[i];
        g_partials[blockIdx.x] = s;
    }
}

__global__ void gqr_finalize(float* __restrict__ out, long long kl_off,
                             float scale, int nblocks)
{
    __shared__ float red[16];
    float s = 0.0f;
    for (int i = threadIdx.x; i < nblocks; i += blockDim.x) s += g_partials[i];
    #pragma unroll
    for (int o = 16; o > 0; o >>= 1)
        s += __shfl_down_sync(0xFFFFFFFFu, s, o);
    if ((threadIdx.x & 31) == 0) red[threadIdx.x >> 5] = s;
    __syncthreads();
    if (threadIdx.x == 0) {
        float t = 0.0f;
        int nw = blockDim.x >> 5;
        for (int i = 0; i < nw; i++) t += red[i];
        out[kl_off] = t * scale;
    }
}

extern "C" void kernel_launch(void* const* d_in, const int* in_sizes, int n_in,
                              void* d_out, int out_size)
{
    const float* z     = (const float*)d_in[0];
    // d_in[1] (noise) is provably unused by the forward values.
    const float* prior = (const float*)d_in[2];
    float* out = (float*)d_out;

    int nrows = in_sizes[0] / 16;                       // 131072
    long long idx_off = (long long)out_size - (long long)nrows;
    if (idx_off < 1) idx_off = 1;
    long long kl_off  = idx_off - 1;

    int npr = nrows >> 1;
    int nblocks = (npr + THREADS - 1) / THREADS;        // 256
    if (nblocks > MAXBLK) nblocks = MAXBLK;             // defensive

    (void)cudaFuncSetAttribute(gqr_main,
                               cudaFuncAttributeMaxDynamicSharedMemorySize, 65536);
    gqr_main<<<nblocks, THREADS, 65536>>>(z, prior, out, nrows, idx_off);

    float scale = (1.4426f * 0.5f) / (float)nrows;
    gqr_finalize<<<1, 512>>>(out, kl_off, scale, nblocks);
}